// round 15
// baseline (speedup 1.0000x reference)
#include <cuda_runtime.h>
#include <cuda_bf16.h>
#include <math.h>
#include <stdint.h>

typedef __nv_bfloat16 bf16;

#define HID   2048
#define NH    16
#define NKV   4
#define HD    128
#define SEQ   2048
#define BATCH 2
#define TOKENS (BATCH*SEQ)
#define NC    3072   /* concatenated QKV output width */

// ---------------- scratch (no allocation allowed) ----------------
__device__ float g_C[(size_t)TOKENS * NC];                 // fused QKV GEMM out
__device__ bf16  g_Xh[(size_t)TOKENS * HID],      g_Xl[(size_t)TOKENS * HID];
__device__ bf16  g_Qh[(size_t)TOKENS * NH * HD],  g_Ql[(size_t)TOKENS * NH * HD];
__device__ bf16  g_Kh[(size_t)TOKENS * NKV * HD], g_Kl[(size_t)TOKENS * NKV * HD];
__device__ bf16  g_Vth[(size_t)BATCH * NKV * HD * SEQ], g_Vtl[(size_t)BATCH * NKV * HD * SEQ];
__device__ bf16  g_Oh[(size_t)TOKENS * NH * HD],  g_Ol[(size_t)TOKENS * NH * HD];
__device__ bf16  g_WcTh[(size_t)NC * 2048],  g_WcTl[(size_t)NC * 2048];   // Wq|Wk|Wv transposed
__device__ bf16  g_WoTh[(size_t)2048 * 2048], g_WoTl[(size_t)2048 * 2048];

// ---------------- helpers ----------------
__device__ __forceinline__ uint32_t smem_u32(const void* p) {
    uint32_t a;
    asm("{ .reg .u64 t; cvta.to.shared.u64 t, %1; cvt.u32.u64 %0, t; }" : "=r"(a) : "l"(p));
    return a;
}

#define CP_ASYNC16(dst, src) \
    asm volatile("cp.async.cg.shared.global [%0], [%1], 16;" :: "r"(dst), "l"(src))
#define CP_COMMIT() asm volatile("cp.async.commit_group;" ::: "memory")
#define CP_WAIT(n)  asm volatile("cp.async.wait_group %0;" :: "n"(n) : "memory")

__device__ __forceinline__ void ldsm_x4(uint32_t addr, uint32_t r[4]) {
    asm volatile("ldmatrix.sync.aligned.m8n8.x4.shared.b16 {%0,%1,%2,%3}, [%4];"
                 : "=r"(r[0]), "=r"(r[1]), "=r"(r[2]), "=r"(r[3]) : "r"(addr));
}
__device__ __forceinline__ void ldsm_x2(uint32_t addr, uint32_t r[2]) {
    asm volatile("ldmatrix.sync.aligned.m8n8.x2.shared.b16 {%0,%1}, [%2];"
                 : "=r"(r[0]), "=r"(r[1]) : "r"(addr));
}
__device__ __forceinline__ void mma_bf16(float c[4], const uint32_t a[4], const uint32_t b[2]) {
    asm volatile(
        "mma.sync.aligned.m16n8k16.row.col.f32.bf16.bf16.f32 "
        "{%0,%1,%2,%3}, {%4,%5,%6,%7}, {%8,%9}, {%0,%1,%2,%3};"
        : "+f"(c[0]), "+f"(c[1]), "+f"(c[2]), "+f"(c[3])
        : "r"(a[0]), "r"(a[1]), "r"(a[2]), "r"(a[3]), "r"(b[0]), "r"(b[1]));
}

__device__ __forceinline__ void fsplit2(float x, bf16& h, bf16& l) {
    h = __float2bfloat16(x);
    l = __float2bfloat16(x - __bfloat162float(h));
}
__device__ __forceinline__ uint32_t pack2(bf16 lo, bf16 hi) {
    __nv_bfloat162 t; t.x = lo; t.y = hi;
    return *reinterpret_cast<uint32_t*>(&t);
}

// ---------------- elementwise split: fp32 -> hi/lo planes ----------------
__global__ void split_kernel(const float* __restrict__ in,
                             bf16* __restrict__ hi, bf16* __restrict__ lo) {
    int i = (blockIdx.x * 256 + threadIdx.x) * 4;
    float4 v = *(const float4*)(in + i);
    bf16 h[4], l[4];
    fsplit2(v.x, h[0], l[0]); fsplit2(v.y, h[1], l[1]);
    fsplit2(v.z, h[2], l[2]); fsplit2(v.w, h[3], l[3]);
    *(uint2*)(hi + i) = *(uint2*)h;
    *(uint2*)(lo + i) = *(uint2*)l;
}

// ---------------- weight transpose + split: Wt[n][k] = W[k][n] ----------------
__global__ void transpose_split_kernel(const float* __restrict__ W,
                                       bf16* __restrict__ Wh, bf16* __restrict__ Wl,
                                       int K, int N) {
    __shared__ float t[32][33];
    int x = blockIdx.x * 32 + threadIdx.x;   // n
    int y0 = blockIdx.y * 32;                // k base
#pragma unroll
    for (int i = threadIdx.y; i < 32; i += 8)
        t[i][threadIdx.x] = W[(size_t)(y0 + i) * N + x];
    __syncthreads();
    int xo = y0 + threadIdx.x;               // k
    int yo0 = blockIdx.x * 32;               // n base
#pragma unroll
    for (int i = threadIdx.y; i < 32; i += 8) {
        bf16 h, l;
        fsplit2(t[threadIdx.x][i], h, l);
        Wh[(size_t)(yo0 + i) * K + xo] = h;
        Wl[(size_t)(yo0 + i) * K + xo] = l;
    }
}

// ---------------- V transpose + split from fused C: Vt[(b,kv,d)][s] ----------------
__global__ void vtrans_kernel(const float* __restrict__ C,
                              bf16* __restrict__ Vth, bf16* __restrict__ Vtl) {
    __shared__ float t[32][33];
    const int bkv = blockIdx.z;
    const int bb = bkv >> 2, kv = bkv & 3;
    const int s0 = blockIdx.x * 32, d0 = blockIdx.y * 32;
#pragma unroll
    for (int i = threadIdx.y; i < 32; i += 8)
        t[i][threadIdx.x] = C[(size_t)(bb * SEQ + s0 + i) * NC + 2560 + kv * HD + d0 + threadIdx.x];
    __syncthreads();
#pragma unroll
    for (int i = threadIdx.y; i < 32; i += 8) {
        bf16 h, l;
        fsplit2(t[threadIdx.x][i], h, l);
        size_t idx = (size_t)(bkv * HD + d0 + i) * SEQ + s0 + threadIdx.x;
        Vth[idx] = h; Vtl[idx] = l;
    }
}

// ---------------- bf16x3 GEMM: C[M,N] = A[M,K] @ Bt[N,K]^T ----------------
#define GROWB 80
#define GPLANE (128 * GROWB)
#define GSTAGE_BYTES (4 * GPLANE)
#define GM_SMEM_BYTES (2 * GSTAGE_BYTES)

__global__ __launch_bounds__(256, 2)
void bf16x3_gemm_kernel(const bf16* __restrict__ Ah, const bf16* __restrict__ Al,
                        const bf16* __restrict__ Bh, const bf16* __restrict__ Bl,
                        float* __restrict__ C, int M, int N, int K) {
    extern __shared__ char gsm[];
    const uint32_t sbase = smem_u32(gsm);

    const int tid = threadIdx.x;
    const int wid = tid >> 5, l = tid & 31;
    const int wm = wid >> 2, wn = wid & 3;
    const int bn = blockIdx.x, bm = blockIdx.y;

    const bf16* src[4] = { Ah + (size_t)bm * 128 * K, Al + (size_t)bm * 128 * K,
                           Bh + (size_t)bn * 128 * K, Bl + (size_t)bn * 128 * K };
    const int KT = K >> 5;

    const int a_sel = l & 15;
    const uint32_t a_kB = (uint32_t)(l >> 4) * 16;
    const int b_sel = l & 7;
    const uint32_t b_kB = (uint32_t)((l >> 3) & 1) * 16;

    float acc[4][4][4];
#pragma unroll
    for (int mt = 0; mt < 4; mt++)
#pragma unroll
        for (int nt = 0; nt < 4; nt++)
#pragma unroll
            for (int r = 0; r < 4; r++) acc[mt][nt][r] = 0.f;

    auto load_stage = [&](int s, int kt) {
        uint32_t base = sbase + s * GSTAGE_BYTES;
        int k0 = kt << 5;
#pragma unroll
        for (int pl = 0; pl < 4; pl++)
#pragma unroll
            for (int half = 0; half < 2; half++) {
                int cid = half * 256 + tid;
                int row = cid >> 2, ch = cid & 3;
                CP_ASYNC16(base + pl * GPLANE + row * GROWB + ch * 16,
                           src[pl] + (size_t)row * K + k0 + ch * 8);
            }
    };

    load_stage(0, 0);
    CP_COMMIT();

    for (int kt = 0; kt < KT; kt++) {
        const int s = kt & 1;
        CP_WAIT(0);
        __syncthreads();
        if (kt + 1 < KT) { load_stage(s ^ 1, kt + 1); CP_COMMIT(); }

        const uint32_t base = sbase + s * GSTAGE_BYTES;

#pragma unroll
        for (int ks = 0; ks < 2; ks++) {
            const uint32_t kB = ks * 32;
            uint32_t bh[4][2], bl[4][2];
#pragma unroll
            for (int nt = 0; nt < 4; nt++) {
                uint32_t boff = (wn * 32 + nt * 8 + b_sel) * GROWB + kB + b_kB;
                ldsm_x2(base + 2 * GPLANE + boff, bh[nt]);
                ldsm_x2(base + 3 * GPLANE + boff, bl[nt]);
            }
#pragma unroll
            for (int mt = 0; mt < 4; mt++) {
                uint32_t ah[4], al[4];
                uint32_t aoff = (wm * 64 + mt * 16 + a_sel) * GROWB + kB + a_kB;
                ldsm_x4(base + aoff, ah);
                ldsm_x4(base + GPLANE + aoff, al);
#pragma unroll
                for (int nt = 0; nt < 4; nt++) {
                    mma_bf16(acc[mt][nt], al, bh[nt]);
                    mma_bf16(acc[mt][nt], ah, bl[nt]);
                    mma_bf16(acc[mt][nt], ah, bh[nt]);
                }
            }
        }
        __syncthreads();
    }

    const int er = l >> 2, ec = (l & 3) * 2;
#pragma unroll
    for (int mt = 0; mt < 4; mt++) {
        int row = bm * 128 + wm * 64 + mt * 16 + er;
#pragma unroll
        for (int nt = 0; nt < 4; nt++) {
            int col = bn * 128 + wn * 32 + nt * 8 + ec;
            *(float2*)(C + (size_t)row * N + col) =
                make_float2(acc[mt][nt][0], acc[mt][nt][1]);
            *(float2*)(C + (size_t)(row + 8) * N + col) =
                make_float2(acc[mt][nt][2], acc[mt][nt][3]);
        }
    }
}

// ---------------- fused RMSNorm + RoPE (reads fused C) -> bf16 hi/lo planes ----------------
__global__ void rmsnorm_rope_kernel(const float* __restrict__ C, int in_off,
                                    bf16* __restrict__ Xh, bf16* __restrict__ Xl,
                                    const float* __restrict__ w,
                                    const float* __restrict__ cs, const float* __restrict__ sn,
                                    int nheads) {
    const int tok = blockIdx.x;
    const int h   = blockIdx.y;
    const int d   = threadIdx.x;
    const int s   = tok & (SEQ - 1);

    const float* row = C + (size_t)tok * NC + in_off + h * HD;
    float x = row[d];

    float ss = x * x;
#pragma unroll
    for (int o = 16; o > 0; o >>= 1) ss += __shfl_xor_sync(0xffffffffu, ss, o);

    __shared__ float wsum[4];
    __shared__ float sv[HD];
    if ((d & 31) == 0) wsum[d >> 5] = ss;
    __syncthreads();
    float tot = wsum[0] + wsum[1] + wsum[2] + wsum[3];
    float r = rsqrtf(tot * (1.0f / HD) + 1e-6f);
    float v = x * r * w[d];
    sv[d] = v;
    __syncthreads();
    float rot = (d < 64) ? -sv[d + 64] : sv[d - 64];
    float y = v * cs[(size_t)s * HD + d] + rot * sn[(size_t)s * HD + d];
    bf16 hh, ll;
    fsplit2(y, hh, ll);
    size_t idx = (size_t)tok * nheads * HD + h * HD + d;
    Xh[idx] = hh; Xl[idx] = ll;
}

// ---------------- tensor-core causal flash attention (bf16x3), warp-owned rows ----------------
// CTA: 128 q rows, 8 warps x 16 rows. Per iter: 64 kv, double-buffered cp.async.
// P kept in registers (C-fragment -> A-fragment reuse). All softmax warp-local.
#define FQ_S 272                              /* Q/K row stride bytes */
#define FV_S 144                              /* V row stride bytes */
#define QPL (128 * FQ_S)                      /* 34816 per Q plane */
#define KPL (64 * FQ_S)                       /* 17408 per K plane */
#define VPL (128 * FV_S)                      /* 18432 per V plane */
#define OFF_K0 (2 * QPL)
#define KV_STAGE (2 * KPL + 2 * VPL)          /* 71680 */
#define FLASH_SMEM_BYTES (2 * QPL + 2 * KV_STAGE)   /* 212992 */

__global__ __launch_bounds__(256, 1)
void flash_kernel(const bf16* __restrict__ Qh, const bf16* __restrict__ Ql,
                  const bf16* __restrict__ Kh, const bf16* __restrict__ Kl,
                  const bf16* __restrict__ Vth, const bf16* __restrict__ Vtl,
                  bf16* __restrict__ Oh, bf16* __restrict__ Ol) {
    extern __shared__ char fsmc[];
    const uint32_t sb = smem_u32(fsmc);

    const int qt = blockIdx.x, h = blockIdx.y, b = blockIdx.z;
    const int kvh = h >> 2;
    const int tid = threadIdx.x, wid = tid >> 5, l = tid & 31;
    const float scale = 0.08838834764831845f;

    const int a_sel = l & 15;
    const uint32_t a_kB = (uint32_t)(l >> 4) * 16;
    const int b4 = ((l >> 4) & 1) * 8 + (l & 7);       // x4 B: two n8 tiles per load
    const uint32_t b_kB = (uint32_t)((l >> 3) & 1) * 16;
    const int qrow = l >> 2, qcol = (l & 3) * 2;

    // Q tiles (both planes), once
    {
        const bf16* qsrc[2] = { Qh + (size_t)(b * SEQ + qt * 128) * (NH * HD) + h * HD,
                                Ql + (size_t)(b * SEQ + qt * 128) * (NH * HD) + h * HD };
#pragma unroll
        for (int t = 0; t < 16; t++) {
            int c = tid + t * 256;
            int pl = c >> 11, cid = c & 2047;
            int r = cid >> 4, ch = cid & 15;
            CP_ASYNC16(sb + pl * QPL + r * FQ_S + ch * 16,
                       qsrc[pl] + (size_t)r * (NH * HD) + ch * 8);
        }
    }
    CP_COMMIT();

    const bf16* ksrc[2] = { Kh + (size_t)(b * SEQ) * (NKV * HD) + kvh * HD,
                            Kl + (size_t)(b * SEQ) * (NKV * HD) + kvh * HD };
    const bf16* vsrc[2] = { Vth + (size_t)(b * NKV + kvh) * HD * SEQ,
                            Vtl + (size_t)(b * NKV + kvh) * HD * SEQ };

    auto load_kv = [&](int jt, int st) {
        uint32_t kb = sb + OFF_K0 + st * KV_STAGE;
        uint32_t vb = kb + 2 * KPL;
#pragma unroll
        for (int t = 0; t < 8; t++) {
            int c = tid + t * 256;
            int pl = c >> 10, cid = c & 1023;
            int r = cid >> 4, ch = cid & 15;
            CP_ASYNC16(kb + pl * KPL + r * FQ_S + ch * 16,
                       ksrc[pl] + (size_t)(jt * 64 + r) * (NKV * HD) + ch * 8);
        }
#pragma unroll
        for (int t = 0; t < 8; t++) {
            int c = tid + t * 256;
            int pl = c >> 10, cid = c & 1023;
            int r = cid >> 3, ch = cid & 7;
            CP_ASYNC16(vb + pl * VPL + r * FV_S + ch * 16,
                       vsrc[pl] + (size_t)r * SEQ + jt * 64 + ch * 8);
        }
    };
    load_kv(0, 0);
    CP_COMMIT();

    float m[2] = { -1e30f, -1e30f }, lsum[2] = { 0.f, 0.f };
    float oacc[16][4];
#pragma unroll
    for (int nto = 0; nto < 16; nto++)
#pragma unroll
        for (int e = 0; e < 4; e++) oacc[nto][e] = 0.f;

    const int jt_end = 2 * qt + 2;
    for (int jt = 0; jt < jt_end; jt++) {
        const int st = jt & 1;
        CP_WAIT(0);
        __syncthreads();
        if (jt + 1 < jt_end) { load_kv(jt + 1, st ^ 1); CP_COMMIT(); }
        const uint32_t kb = sb + OFF_K0 + st * KV_STAGE;
        const uint32_t vb = kb + 2 * KPL;

        // S = Q @ K^T : warp stripe 16x64, 8 k16 steps, 3-term
        float sacc[8][4];
#pragma unroll
        for (int nt = 0; nt < 8; nt++)
#pragma unroll
            for (int e = 0; e < 4; e++) sacc[nt][e] = 0.f;

#pragma unroll
        for (int ks = 0; ks < 8; ks++) {
            const uint32_t kB = ks * 32;
            uint32_t ah[4], al[4];
            uint32_t aoff = (uint32_t)(wid * 16 + a_sel) * FQ_S + kB + a_kB;
            ldsm_x4(sb + aoff, ah);
            ldsm_x4(sb + QPL + aoff, al);
#pragma unroll
            for (int ntp = 0; ntp < 4; ntp++) {
                uint32_t bh4[4], bl4[4];
                uint32_t boff = (uint32_t)(ntp * 16 + b4) * FQ_S + kB + b_kB;
                ldsm_x4(kb + boff, bh4);
                ldsm_x4(kb + KPL + boff, bl4);
                mma_bf16(sacc[2 * ntp],     al, bh4);
                mma_bf16(sacc[2 * ntp],     ah, bl4);
                mma_bf16(sacc[2 * ntp],     ah, bh4);
                mma_bf16(sacc[2 * ntp + 1], al, bh4 + 2);
                mma_bf16(sacc[2 * ntp + 1], ah, bl4 + 2);
                mma_bf16(sacc[2 * ntp + 1], ah, bh4 + 2);
            }
        }

        // scale + causal mask + warp-local row max
        const bool need_mask = (jt >= 2 * qt);
        float lmax[2] = { -1e30f, -1e30f };
#pragma unroll
        for (int nt = 0; nt < 8; nt++)
#pragma unroll
            for (int e = 0; e < 4; e++) {
                int h2 = e >> 1;
                float val = sacc[nt][e] * scale;
                if (need_mask) {
                    int gr = qt * 128 + wid * 16 + qrow + 8 * h2;
                    int gc = jt * 64 + nt * 8 + qcol + (e & 1);
                    if (gc > gr) val = -1e30f;
                }
                sacc[nt][e] = val;
                lmax[h2] = fmaxf(lmax[h2], val);
            }

        float alpha[2];
#pragma unroll
        for (int h2 = 0; h2 < 2; h2++) {
            float v = lmax[h2];
            v = fmaxf(v, __shfl_xor_sync(0xffffffffu, v, 1));
            v = fmaxf(v, __shfl_xor_sync(0xffffffffu, v, 2));
            float mn = fmaxf(m[h2], v);
            alpha[h2] = __expf(m[h2] - mn);
            m[h2] = mn;
        }

        // p = exp(s-m): pack A-fragments (hi/lo) in registers
        float ls[2] = { 0.f, 0.f };
        uint32_t pfh[4][4], pfl[4][4];
#pragma unroll
        for (int ks2 = 0; ks2 < 4; ks2++)
#pragma unroll
            for (int half = 0; half < 2; half++) {
                int nt = 2 * ks2 + half;
                float p0 = __expf(sacc[nt][0] - m[0]);
                float p1 = __expf(sacc[nt][1] - m[0]);
                float p2 = __expf(sacc[nt][2] - m[1]);
                float p3 = __expf(sacc[nt][3] - m[1]);
                ls[0] += p0 + p1;
                ls[1] += p2 + p3;
                bf16 a0 = __float2bfloat16(p0), a1 = __float2bfloat16(p1);
                bf16 a2 = __float2bfloat16(p2), a3 = __float2bfloat16(p3);
                pfh[ks2][half * 2 + 0] = pack2(a0, a1);
                pfh[ks2][half * 2 + 1] = pack2(a2, a3);
                pfl[ks2][half * 2 + 0] =
                    pack2(__float2bfloat16(p0 - __bfloat162float(a0)),
                          __float2bfloat16(p1 - __bfloat162float(a1)));
                pfl[ks2][half * 2 + 1] =
                    pack2(__float2bfloat16(p2 - __bfloat162float(a2)),
                          __float2bfloat16(p3 - __bfloat162float(a3)));
            }
#pragma unroll
        for (int h2 = 0; h2 < 2; h2++) {
            float v = ls[h2];
            v += __shfl_xor_sync(0xffffffffu, v, 1);
            v += __shfl_xor_sync(0xffffffffu, v, 2);
            lsum[h2] = lsum[h2] * alpha[h2] + v;
        }
#pragma unroll
        for (int nto = 0; nto < 16; nto++)
#pragma unroll
            for (int e = 0; e < 4; e++) oacc[nto][e] *= alpha[e >> 1];

        // O += P @ V : 4 k16 steps over s, 16 n8 tiles over d, 3-term
#pragma unroll
        for (int ks2 = 0; ks2 < 4; ks2++) {
            const uint32_t kB = ks2 * 32;
#pragma unroll
            for (int ntp = 0; ntp < 8; ntp++) {
                uint32_t vh4[4], vl4[4];
                uint32_t boff = (uint32_t)(ntp * 16 + b4) * FV_S + kB + b_kB;
                ldsm_x4(vb + boff, vh4);
                ldsm_x4(vb + VPL + boff, vl4);
                mma_bf16(oacc[2 * ntp],     pfl[ks2], vh4);
                mma_bf16(oacc[2 * ntp],     pfh[ks2], vl4);
                mma_bf16(oacc[2 * ntp],     pfh[ks2], vh4);
                mma_bf16(oacc[2 * ntp + 1], pfl[ks2], vh4 + 2);
                mma_bf16(oacc[2 * ntp + 1], pfh[ks2], vl4 + 2);
                mma_bf16(oacc[2 * ntp + 1], pfh[ks2], vh4 + 2);
            }
        }
    }

    // epilogue: normalize, split, store hi/lo planes
    bf16* Ogh = Oh + (size_t)(b * SEQ + qt * 128) * (NH * HD) + h * HD;
    bf16* Ogl = Ol + (size_t)(b * SEQ + qt * 128) * (NH * HD) + h * HD;
#pragma unroll
    for (int h2 = 0; h2 < 2; h2++) {
        int r = wid * 16 + qrow + 8 * h2;
        float inv = 1.0f / lsum[h2];
#pragma unroll
        for (int nto = 0; nto < 16; nto++) {
            int c = nto * 8 + qcol;
            float v0 = oacc[nto][h2 * 2 + 0] * inv;
            float v1 = oacc[nto][h2 * 2 + 1] * inv;
            bf16 h0 = __float2bfloat16(v0), h1b = __float2bfloat16(v1);
            *(uint32_t*)(Ogh + (size_t)r * (NH * HD) + c) = pack2(h0, h1b);
            *(uint32_t*)(Ogl + (size_t)r * (NH * HD) + c) =
                pack2(__float2bfloat16(v0 - __bfloat162float(h0)),
                      __float2bfloat16(v1 - __bfloat162float(h1b)));
        }
    }
}

// ---------------- launch ----------------
extern "C" void kernel_launch(void* const* d_in, const int* in_sizes, int n_in,
                              void* d_out, int out_size) {
    const float* X  = (const float*)d_in[0];
    const float* cs = (const float*)d_in[1];
    const float* sn = (const float*)d_in[2];
    const float* Wq = (const float*)d_in[3];
    const float* Wk = (const float*)d_in[4];
    const float* Wv = (const float*)d_in[5];
    const float* Wo = (const float*)d_in[6];
    const float* qw = (const float*)d_in[7];
    const float* kw = (const float*)d_in[8];
    float* out = (float*)d_out;

    float* C;
    bf16 *Xh, *Xl, *Qh, *Ql, *Kh, *Kl, *Vth, *Vtl, *Oh, *Ol;
    bf16 *WcTh, *WcTl, *WoTh, *WoTl;
    cudaGetSymbolAddress((void**)&C,   g_C);
    cudaGetSymbolAddress((void**)&Xh,  g_Xh);  cudaGetSymbolAddress((void**)&Xl,  g_Xl);
    cudaGetSymbolAddress((void**)&Qh,  g_Qh);  cudaGetSymbolAddress((void**)&Ql,  g_Ql);
    cudaGetSymbolAddress((void**)&Kh,  g_Kh);  cudaGetSymbolAddress((void**)&Kl,  g_Kl);
    cudaGetSymbolAddress((void**)&Vth, g_Vth); cudaGetSymbolAddress((void**)&Vtl, g_Vtl);
    cudaGetSymbolAddress((void**)&Oh,  g_Oh);  cudaGetSymbolAddress((void**)&Ol,  g_Ol);
    cudaGetSymbolAddress((void**)&WcTh, g_WcTh); cudaGetSymbolAddress((void**)&WcTl, g_WcTl);
    cudaGetSymbolAddress((void**)&WoTh, g_WoTh); cudaGetSymbolAddress((void**)&WoTl, g_WoTl);

    cudaFuncSetAttribute(bf16x3_gemm_kernel, cudaFuncAttributeMaxDynamicSharedMemorySize,
                         GM_SMEM_BYTES);
    cudaFuncSetAttribute(flash_kernel, cudaFuncAttributeMaxDynamicSharedMemorySize,
                         FLASH_SMEM_BYTES);

    // operand preparation (weights concatenated into one [3072][2048] operand)
    split_kernel<<<(TOKENS * HID) / 1024, 256>>>(X, Xh, Xl);
    transpose_split_kernel<<<dim3(2048 / 32, 2048 / 32), dim3(32, 8)>>>(
        Wq, WcTh, WcTl, 2048, 2048);
    transpose_split_kernel<<<dim3(512 / 32, 2048 / 32), dim3(32, 8)>>>(
        Wk, WcTh + (size_t)2048 * 2048, WcTl + (size_t)2048 * 2048, 2048, 512);
    transpose_split_kernel<<<dim3(512 / 32, 2048 / 32), dim3(32, 8)>>>(
        Wv, WcTh + (size_t)2560 * 2048, WcTl + (size_t)2560 * 2048, 2048, 512);
    transpose_split_kernel<<<dim3(2048 / 32, 2048 / 32), dim3(32, 8)>>>(
        Wo, WoTh, WoTl, 2048, 2048);

    // fused QKV projection: C[tok][0:2048]=Q, [2048:2560]=K, [2560:3072]=V
    bf16x3_gemm_kernel<<<dim3(NC / 128, TOKENS / 128), 256, GM_SMEM_BYTES>>>(
        Xh, Xl, WcTh, WcTl, C, TOKENS, NC, HID);

    // RMSNorm + RoPE -> planes; V transpose + split
    rmsnorm_rope_kernel<<<dim3(TOKENS, NH),  HD>>>(C, 0,    Qh, Ql, qw, cs, sn, NH);
    rmsnorm_rope_kernel<<<dim3(TOKENS, NKV), HD>>>(C, 2048, Kh, Kl, kw, cs, sn, NKV);
    vtrans_kernel<<<dim3(SEQ / 32, HD / 32, BATCH * NKV), dim3(32, 8)>>>(C, Vth, Vtl);

    // causal GQA flash attention (register-P, double-buffered)
    flash_kernel<<<dim3(SEQ / 128, NH, BATCH), 256, FLASH_SMEM_BYTES>>>(
        Qh, Ql, Kh, Kl, Vth, Vtl, Oh, Ol);

    // output projection
    bf16x3_gemm_kernel<<<dim3(2048 / 128, TOKENS / 128), 256, GM_SMEM_BYTES>>>(
        Oh, Ol, WoTh, WoTl, out, TOKENS, 2048, HID);
}

// round 16
// speedup vs baseline: 1.0011x; 1.0011x over previous
#include <cuda_runtime.h>
#include <cuda_bf16.h>
#include <math.h>
#include <stdint.h>

typedef __nv_bfloat16 bf16;

#define HID   2048
#define NH    16
#define NKV   4
#define HD    128
#define SEQ   2048
#define BATCH 2
#define TOKENS (BATCH*SEQ)
#define NC    3072   /* concatenated QKV output width */

// ---------------- scratch (no allocation allowed) ----------------
__device__ float g_C[(size_t)TOKENS * NC];                 // fused QKV GEMM out
__device__ bf16  g_Xh[(size_t)TOKENS * HID],      g_Xl[(size_t)TOKENS * HID];
__device__ bf16  g_Qh[(size_t)TOKENS * NH * HD],  g_Ql[(size_t)TOKENS * NH * HD];
__device__ bf16  g_Kh[(size_t)TOKENS * NKV * HD], g_Kl[(size_t)TOKENS * NKV * HD];
__device__ bf16  g_Vth[(size_t)BATCH * NKV * HD * SEQ], g_Vtl[(size_t)BATCH * NKV * HD * SEQ];
__device__ bf16  g_Oh[(size_t)TOKENS * NH * HD],  g_Ol[(size_t)TOKENS * NH * HD];
__device__ bf16  g_WcTh[(size_t)NC * 2048],  g_WcTl[(size_t)NC * 2048];   // Wq|Wk|Wv transposed
__device__ bf16  g_WoTh[(size_t)2048 * 2048], g_WoTl[(size_t)2048 * 2048];

// ---------------- helpers ----------------
__device__ __forceinline__ uint32_t smem_u32(const void* p) {
    uint32_t a;
    asm("{ .reg .u64 t; cvta.to.shared.u64 t, %1; cvt.u32.u64 %0, t; }" : "=r"(a) : "l"(p));
    return a;
}

#define CP_ASYNC16(dst, src) \
    asm volatile("cp.async.cg.shared.global [%0], [%1], 16;" :: "r"(dst), "l"(src))
#define CP_COMMIT() asm volatile("cp.async.commit_group;" ::: "memory")
#define CP_WAIT(n)  asm volatile("cp.async.wait_group %0;" :: "n"(n) : "memory")

__device__ __forceinline__ void ldsm_x4(uint32_t addr, uint32_t r[4]) {
    asm volatile("ldmatrix.sync.aligned.m8n8.x4.shared.b16 {%0,%1,%2,%3}, [%4];"
                 : "=r"(r[0]), "=r"(r[1]), "=r"(r[2]), "=r"(r[3]) : "r"(addr));
}
__device__ __forceinline__ void ldsm_x2(uint32_t addr, uint32_t r[2]) {
    asm volatile("ldmatrix.sync.aligned.m8n8.x2.shared.b16 {%0,%1}, [%2];"
                 : "=r"(r[0]), "=r"(r[1]) : "r"(addr));
}
__device__ __forceinline__ void mma_bf16(float c[4], const uint32_t a[4], const uint32_t b[2]) {
    asm volatile(
        "mma.sync.aligned.m16n8k16.row.col.f32.bf16.bf16.f32 "
        "{%0,%1,%2,%3}, {%4,%5,%6,%7}, {%8,%9}, {%0,%1,%2,%3};"
        : "+f"(c[0]), "+f"(c[1]), "+f"(c[2]), "+f"(c[3])
        : "r"(a[0]), "r"(a[1]), "r"(a[2]), "r"(a[3]), "r"(b[0]), "r"(b[1]));
}

__device__ __forceinline__ void fsplit2(float x, bf16& h, bf16& l) {
    h = __float2bfloat16(x);
    l = __float2bfloat16(x - __bfloat162float(h));
}
__device__ __forceinline__ uint32_t pack2(bf16 lo, bf16 hi) {
    __nv_bfloat162 t; t.x = lo; t.y = hi;
    return *reinterpret_cast<uint32_t*>(&t);
}

// ---------------- elementwise split: fp32 -> hi/lo planes ----------------
__global__ void split_kernel(const float* __restrict__ in,
                             bf16* __restrict__ hi, bf16* __restrict__ lo) {
    int i = (blockIdx.x * 256 + threadIdx.x) * 4;
    float4 v = *(const float4*)(in + i);
    bf16 h[4], l[4];
    fsplit2(v.x, h[0], l[0]); fsplit2(v.y, h[1], l[1]);
    fsplit2(v.z, h[2], l[2]); fsplit2(v.w, h[3], l[3]);
    *(uint2*)(hi + i) = *(uint2*)h;
    *(uint2*)(lo + i) = *(uint2*)l;
}

// ---------------- weight transpose + split: Wt[n][k] = W[k][n] ----------------
__global__ void transpose_split_kernel(const float* __restrict__ W,
                                       bf16* __restrict__ Wh, bf16* __restrict__ Wl,
                                       int K, int N) {
    __shared__ float t[32][33];
    int x = blockIdx.x * 32 + threadIdx.x;   // n
    int y0 = blockIdx.y * 32;                // k base
#pragma unroll
    for (int i = threadIdx.y; i < 32; i += 8)
        t[i][threadIdx.x] = W[(size_t)(y0 + i) * N + x];
    __syncthreads();
    int xo = y0 + threadIdx.x;               // k
    int yo0 = blockIdx.x * 32;               // n base
#pragma unroll
    for (int i = threadIdx.y; i < 32; i += 8) {
        bf16 h, l;
        fsplit2(t[threadIdx.x][i], h, l);
        Wh[(size_t)(yo0 + i) * K + xo] = h;
        Wl[(size_t)(yo0 + i) * K + xo] = l;
    }
}

// ---------------- V transpose + split from fused C: Vt[(b,kv,d)][s] ----------------
__global__ void vtrans_kernel(const float* __restrict__ C,
                              bf16* __restrict__ Vth, bf16* __restrict__ Vtl) {
    __shared__ float t[32][33];
    const int bkv = blockIdx.z;
    const int bb = bkv >> 2, kv = bkv & 3;
    const int s0 = blockIdx.x * 32, d0 = blockIdx.y * 32;
#pragma unroll
    for (int i = threadIdx.y; i < 32; i += 8)
        t[i][threadIdx.x] = C[(size_t)(bb * SEQ + s0 + i) * NC + 2560 + kv * HD + d0 + threadIdx.x];
    __syncthreads();
#pragma unroll
    for (int i = threadIdx.y; i < 32; i += 8) {
        bf16 h, l;
        fsplit2(t[threadIdx.x][i], h, l);
        size_t idx = (size_t)(bkv * HD + d0 + i) * SEQ + s0 + threadIdx.x;
        Vth[idx] = h; Vtl[idx] = l;
    }
}

// ---------------- bf16x3 GEMM: C[M,N] = A[M,K] @ Bt[N,K]^T ----------------
#define GROWB 80
#define GPLANE (128 * GROWB)
#define GSTAGE_BYTES (4 * GPLANE)
#define GM_SMEM_BYTES (2 * GSTAGE_BYTES)

__global__ __launch_bounds__(256, 2)
void bf16x3_gemm_kernel(const bf16* __restrict__ Ah, const bf16* __restrict__ Al,
                        const bf16* __restrict__ Bh, const bf16* __restrict__ Bl,
                        float* __restrict__ C, int M, int N, int K) {
    extern __shared__ char gsm[];
    const uint32_t sbase = smem_u32(gsm);

    const int tid = threadIdx.x;
    const int wid = tid >> 5, l = tid & 31;
    const int wm = wid >> 2, wn = wid & 3;
    const int bn = blockIdx.x, bm = blockIdx.y;

    const bf16* src[4] = { Ah + (size_t)bm * 128 * K, Al + (size_t)bm * 128 * K,
                           Bh + (size_t)bn * 128 * K, Bl + (size_t)bn * 128 * K };
    const int KT = K >> 5;

    const int a_sel = l & 15;
    const uint32_t a_kB = (uint32_t)(l >> 4) * 16;
    const int b_sel = l & 7;
    const uint32_t b_kB = (uint32_t)((l >> 3) & 1) * 16;

    float acc[4][4][4];
#pragma unroll
    for (int mt = 0; mt < 4; mt++)
#pragma unroll
        for (int nt = 0; nt < 4; nt++)
#pragma unroll
            for (int r = 0; r < 4; r++) acc[mt][nt][r] = 0.f;

    auto load_stage = [&](int s, int kt) {
        uint32_t base = sbase + s * GSTAGE_BYTES;
        int k0 = kt << 5;
#pragma unroll
        for (int pl = 0; pl < 4; pl++)
#pragma unroll
            for (int half = 0; half < 2; half++) {
                int cid = half * 256 + tid;
                int row = cid >> 2, ch = cid & 3;
                CP_ASYNC16(base + pl * GPLANE + row * GROWB + ch * 16,
                           src[pl] + (size_t)row * K + k0 + ch * 8);
            }
    };

    load_stage(0, 0);
    CP_COMMIT();

    for (int kt = 0; kt < KT; kt++) {
        const int s = kt & 1;
        CP_WAIT(0);
        __syncthreads();
        if (kt + 1 < KT) { load_stage(s ^ 1, kt + 1); CP_COMMIT(); }

        const uint32_t base = sbase + s * GSTAGE_BYTES;

#pragma unroll
        for (int ks = 0; ks < 2; ks++) {
            const uint32_t kB = ks * 32;
            uint32_t bh[4][2], bl[4][2];
#pragma unroll
            for (int nt = 0; nt < 4; nt++) {
                uint32_t boff = (wn * 32 + nt * 8 + b_sel) * GROWB + kB + b_kB;
                ldsm_x2(base + 2 * GPLANE + boff, bh[nt]);
                ldsm_x2(base + 3 * GPLANE + boff, bl[nt]);
            }
#pragma unroll
            for (int mt = 0; mt < 4; mt++) {
                uint32_t ah[4], al[4];
                uint32_t aoff = (wm * 64 + mt * 16 + a_sel) * GROWB + kB + a_kB;
                ldsm_x4(base + aoff, ah);
                ldsm_x4(base + GPLANE + aoff, al);
#pragma unroll
                for (int nt = 0; nt < 4; nt++) {
                    mma_bf16(acc[mt][nt], al, bh[nt]);
                    mma_bf16(acc[mt][nt], ah, bl[nt]);
                    mma_bf16(acc[mt][nt], ah, bh[nt]);
                }
            }
        }
        __syncthreads();
    }

    const int er = l >> 2, ec = (l & 3) * 2;
#pragma unroll
    for (int mt = 0; mt < 4; mt++) {
        int row = bm * 128 + wm * 64 + mt * 16 + er;
#pragma unroll
        for (int nt = 0; nt < 4; nt++) {
            int col = bn * 128 + wn * 32 + nt * 8 + ec;
            *(float2*)(C + (size_t)row * N + col) =
                make_float2(acc[mt][nt][0], acc[mt][nt][1]);
            *(float2*)(C + (size_t)(row + 8) * N + col) =
                make_float2(acc[mt][nt][2], acc[mt][nt][3]);
        }
    }
}

// ---------------- fused RMSNorm + RoPE (reads fused C) -> bf16 hi/lo planes ----------------
__global__ void rmsnorm_rope_kernel(const float* __restrict__ C, int in_off,
                                    bf16* __restrict__ Xh, bf16* __restrict__ Xl,
                                    const float* __restrict__ w,
                                    const float* __restrict__ cs, const float* __restrict__ sn,
                                    int nheads) {
    const int tok = blockIdx.x;
    const int h   = blockIdx.y;
    const int d   = threadIdx.x;
    const int s   = tok & (SEQ - 1);

    const float* row = C + (size_t)tok * NC + in_off + h * HD;
    float x = row[d];

    float ss = x * x;
#pragma unroll
    for (int o = 16; o > 0; o >>= 1) ss += __shfl_xor_sync(0xffffffffu, ss, o);

    __shared__ float wsum[4];
    __shared__ float sv[HD];
    if ((d & 31) == 0) wsum[d >> 5] = ss;
    __syncthreads();
    float tot = wsum[0] + wsum[1] + wsum[2] + wsum[3];
    float r = rsqrtf(tot * (1.0f / HD) + 1e-6f);
    float v = x * r * w[d];
    sv[d] = v;
    __syncthreads();
    float rot = (d < 64) ? -sv[d + 64] : sv[d - 64];
    float y = v * cs[(size_t)s * HD + d] + rot * sn[(size_t)s * HD + d];
    bf16 hh, ll;
    fsplit2(y, hh, ll);
    size_t idx = (size_t)tok * nheads * HD + h * HD + d;
    Xh[idx] = hh; Xl[idx] = ll;
}

// ---------------- tensor-core causal flash attention (bf16x3), warp-owned rows ----------------
// CTA: 128 q rows, 8 warps x 16 rows. Per iter: 64 kv, double-buffered cp.async.
// P kept in registers (C-fragment -> A-fragment reuse). All softmax warp-local.
#define FQ_S 272                              /* Q/K row stride bytes */
#define FV_S 144                              /* V row stride bytes */
#define QPL (128 * FQ_S)                      /* 34816 per Q plane */
#define KPL (64 * FQ_S)                       /* 17408 per K plane */
#define VPL (128 * FV_S)                      /* 18432 per V plane */
#define OFF_K0 (2 * QPL)
#define KV_STAGE (2 * KPL + 2 * VPL)          /* 71680 */
#define FLASH_SMEM_BYTES (2 * QPL + 2 * KV_STAGE)   /* 212992 */

__global__ __launch_bounds__(256, 1)
void flash_kernel(const bf16* __restrict__ Qh, const bf16* __restrict__ Ql,
                  const bf16* __restrict__ Kh, const bf16* __restrict__ Kl,
                  const bf16* __restrict__ Vth, const bf16* __restrict__ Vtl,
                  bf16* __restrict__ Oh, bf16* __restrict__ Ol) {
    extern __shared__ char fsmc[];
    const uint32_t sb = smem_u32(fsmc);

    const int qt = blockIdx.x, h = blockIdx.y, b = blockIdx.z;
    const int kvh = h >> 2;
    const int tid = threadIdx.x, wid = tid >> 5, l = tid & 31;
    const float scale = 0.08838834764831845f;

    const int a_sel = l & 15;
    const uint32_t a_kB = (uint32_t)(l >> 4) * 16;
    const int b4 = ((l >> 4) & 1) * 8 + (l & 7);       // x4 B: two n8 tiles per load
    const uint32_t b_kB = (uint32_t)((l >> 3) & 1) * 16;
    const int qrow = l >> 2, qcol = (l & 3) * 2;

    // Q tiles (both planes), once
    {
        const bf16* qsrc[2] = { Qh + (size_t)(b * SEQ + qt * 128) * (NH * HD) + h * HD,
                                Ql + (size_t)(b * SEQ + qt * 128) * (NH * HD) + h * HD };
#pragma unroll
        for (int t = 0; t < 16; t++) {
            int c = tid + t * 256;
            int pl = c >> 11, cid = c & 2047;
            int r = cid >> 4, ch = cid & 15;
            CP_ASYNC16(sb + pl * QPL + r * FQ_S + ch * 16,
                       qsrc[pl] + (size_t)r * (NH * HD) + ch * 8);
        }
    }
    CP_COMMIT();

    const bf16* ksrc[2] = { Kh + (size_t)(b * SEQ) * (NKV * HD) + kvh * HD,
                            Kl + (size_t)(b * SEQ) * (NKV * HD) + kvh * HD };
    const bf16* vsrc[2] = { Vth + (size_t)(b * NKV + kvh) * HD * SEQ,
                            Vtl + (size_t)(b * NKV + kvh) * HD * SEQ };

    auto load_kv = [&](int jt, int st) {
        uint32_t kb = sb + OFF_K0 + st * KV_STAGE;
        uint32_t vb = kb + 2 * KPL;
#pragma unroll
        for (int t = 0; t < 8; t++) {
            int c = tid + t * 256;
            int pl = c >> 10, cid = c & 1023;
            int r = cid >> 4, ch = cid & 15;
            CP_ASYNC16(kb + pl * KPL + r * FQ_S + ch * 16,
                       ksrc[pl] + (size_t)(jt * 64 + r) * (NKV * HD) + ch * 8);
        }
#pragma unroll
        for (int t = 0; t < 8; t++) {
            int c = tid + t * 256;
            int pl = c >> 10, cid = c & 1023;
            int r = cid >> 3, ch = cid & 7;
            CP_ASYNC16(vb + pl * VPL + r * FV_S + ch * 16,
                       vsrc[pl] + (size_t)r * SEQ + jt * 64 + ch * 8);
        }
    };
    load_kv(0, 0);
    CP_COMMIT();

    float m[2] = { -1e30f, -1e30f }, lsum[2] = { 0.f, 0.f };
    float oacc[16][4];
#pragma unroll
    for (int nto = 0; nto < 16; nto++)
#pragma unroll
        for (int e = 0; e < 4; e++) oacc[nto][e] = 0.f;

    const int jt_end = 2 * qt + 2;
    for (int jt = 0; jt < jt_end; jt++) {
        const int st = jt & 1;
        CP_WAIT(0);
        __syncthreads();
        if (jt + 1 < jt_end) { load_kv(jt + 1, st ^ 1); CP_COMMIT(); }
        const uint32_t kb = sb + OFF_K0 + st * KV_STAGE;
        const uint32_t vb = kb + 2 * KPL;

        // S = Q @ K^T : warp stripe 16x64, 8 k16 steps, 3-term
        float sacc[8][4];
#pragma unroll
        for (int nt = 0; nt < 8; nt++)
#pragma unroll
            for (int e = 0; e < 4; e++) sacc[nt][e] = 0.f;

#pragma unroll
        for (int ks = 0; ks < 8; ks++) {
            const uint32_t kB = ks * 32;
            uint32_t ah[4], al[4];
            uint32_t aoff = (uint32_t)(wid * 16 + a_sel) * FQ_S + kB + a_kB;
            ldsm_x4(sb + aoff, ah);
            ldsm_x4(sb + QPL + aoff, al);
#pragma unroll
            for (int ntp = 0; ntp < 4; ntp++) {
                uint32_t bh4[4], bl4[4];
                uint32_t boff = (uint32_t)(ntp * 16 + b4) * FQ_S + kB + b_kB;
                ldsm_x4(kb + boff, bh4);
                ldsm_x4(kb + KPL + boff, bl4);
                mma_bf16(sacc[2 * ntp],     al, bh4);
                mma_bf16(sacc[2 * ntp],     ah, bl4);
                mma_bf16(sacc[2 * ntp],     ah, bh4);
                mma_bf16(sacc[2 * ntp + 1], al, bh4 + 2);
                mma_bf16(sacc[2 * ntp + 1], ah, bl4 + 2);
                mma_bf16(sacc[2 * ntp + 1], ah, bh4 + 2);
            }
        }

        // scale + causal mask + warp-local row max
        const bool need_mask = (jt >= 2 * qt);
        float lmax[2] = { -1e30f, -1e30f };
#pragma unroll
        for (int nt = 0; nt < 8; nt++)
#pragma unroll
            for (int e = 0; e < 4; e++) {
                int h2 = e >> 1;
                float val = sacc[nt][e] * scale;
                if (need_mask) {
                    int gr = qt * 128 + wid * 16 + qrow + 8 * h2;
                    int gc = jt * 64 + nt * 8 + qcol + (e & 1);
                    if (gc > gr) val = -1e30f;
                }
                sacc[nt][e] = val;
                lmax[h2] = fmaxf(lmax[h2], val);
            }

        float alpha[2];
#pragma unroll
        for (int h2 = 0; h2 < 2; h2++) {
            float v = lmax[h2];
            v = fmaxf(v, __shfl_xor_sync(0xffffffffu, v, 1));
            v = fmaxf(v, __shfl_xor_sync(0xffffffffu, v, 2));
            float mn = fmaxf(m[h2], v);
            alpha[h2] = __expf(m[h2] - mn);
            m[h2] = mn;
        }

        // p = exp(s-m): pack A-fragments (hi/lo) in registers
        float ls[2] = { 0.f, 0.f };
        uint32_t pfh[4][4], pfl[4][4];
#pragma unroll
        for (int ks2 = 0; ks2 < 4; ks2++)
#pragma unroll
            for (int half = 0; half < 2; half++) {
                int nt = 2 * ks2 + half;
                float p0 = __expf(sacc[nt][0] - m[0]);
                float p1 = __expf(sacc[nt][1] - m[0]);
                float p2 = __expf(sacc[nt][2] - m[1]);
                float p3 = __expf(sacc[nt][3] - m[1]);
                ls[0] += p0 + p1;
                ls[1] += p2 + p3;
                bf16 a0 = __float2bfloat16(p0), a1 = __float2bfloat16(p1);
                bf16 a2 = __float2bfloat16(p2), a3 = __float2bfloat16(p3);
                pfh[ks2][half * 2 + 0] = pack2(a0, a1);
                pfh[ks2][half * 2 + 1] = pack2(a2, a3);
                pfl[ks2][half * 2 + 0] =
                    pack2(__float2bfloat16(p0 - __bfloat162float(a0)),
                          __float2bfloat16(p1 - __bfloat162float(a1)));
                pfl[ks2][half * 2 + 1] =
                    pack2(__float2bfloat16(p2 - __bfloat162float(a2)),
                          __float2bfloat16(p3 - __bfloat162float(a3)));
            }
#pragma unroll
        for (int h2 = 0; h2 < 2; h2++) {
            float v = ls[h2];
            v += __shfl_xor_sync(0xffffffffu, v, 1);
            v += __shfl_xor_sync(0xffffffffu, v, 2);
            lsum[h2] = lsum[h2] * alpha[h2] + v;
        }
#pragma unroll
        for (int nto = 0; nto < 16; nto++)
#pragma unroll
            for (int e = 0; e < 4; e++) oacc[nto][e] *= alpha[e >> 1];

        // O += P @ V : 4 k16 steps over s, 16 n8 tiles over d, 3-term
#pragma unroll
        for (int ks2 = 0; ks2 < 4; ks2++) {
            const uint32_t kB = ks2 * 32;
#pragma unroll
            for (int ntp = 0; ntp < 8; ntp++) {
                uint32_t vh4[4], vl4[4];
                uint32_t boff = (uint32_t)(ntp * 16 + b4) * FV_S + kB + b_kB;
                ldsm_x4(vb + boff, vh4);
                ldsm_x4(vb + VPL + boff, vl4);
                mma_bf16(oacc[2 * ntp],     pfl[ks2], vh4);
                mma_bf16(oacc[2 * ntp],     pfh[ks2], vl4);
                mma_bf16(oacc[2 * ntp],     pfh[ks2], vh4);
                mma_bf16(oacc[2 * ntp + 1], pfl[ks2], vh4 + 2);
                mma_bf16(oacc[2 * ntp + 1], pfh[ks2], vl4 + 2);
                mma_bf16(oacc[2 * ntp + 1], pfh[ks2], vh4 + 2);
            }
        }
    }

    // epilogue: normalize, split, store hi/lo planes
    bf16* Ogh = Oh + (size_t)(b * SEQ + qt * 128) * (NH * HD) + h * HD;
    bf16* Ogl = Ol + (size_t)(b * SEQ + qt * 128) * (NH * HD) + h * HD;
#pragma unroll
    for (int h2 = 0; h2 < 2; h2++) {
        int r = wid * 16 + qrow + 8 * h2;
        float inv = 1.0f / lsum[h2];
#pragma unroll
        for (int nto = 0; nto < 16; nto++) {
            int c = nto * 8 + qcol;
            float v0 = oacc[nto][h2 * 2 + 0] * inv;
            float v1 = oacc[nto][h2 * 2 + 1] * inv;
            bf16 h0 = __float2bfloat16(v0), h1b = __float2bfloat16(v1);
            *(uint32_t*)(Ogh + (size_t)r * (NH * HD) + c) = pack2(h0, h1b);
            *(uint32_t*)(Ogl + (size_t)r * (NH * HD) + c) =
                pack2(__float2bfloat16(v0 - __bfloat162float(h0)),
                      __float2bfloat16(v1 - __bfloat162float(h1b)));
        }
    }
}

// ---------------- launch ----------------
extern "C" void kernel_launch(void* const* d_in, const int* in_sizes, int n_in,
                              void* d_out, int out_size) {
    const float* X  = (const float*)d_in[0];
    const float* cs = (const float*)d_in[1];
    const float* sn = (const float*)d_in[2];
    const float* Wq = (const float*)d_in[3];
    const float* Wk = (const float*)d_in[4];
    const float* Wv = (const float*)d_in[5];
    const float* Wo = (const float*)d_in[6];
    const float* qw = (const float*)d_in[7];
    const float* kw = (const float*)d_in[8];
    float* out = (float*)d_out;

    float* C;
    bf16 *Xh, *Xl, *Qh, *Ql, *Kh, *Kl, *Vth, *Vtl, *Oh, *Ol;
    bf16 *WcTh, *WcTl, *WoTh, *WoTl;
    cudaGetSymbolAddress((void**)&C,   g_C);
    cudaGetSymbolAddress((void**)&Xh,  g_Xh);  cudaGetSymbolAddress((void**)&Xl,  g_Xl);
    cudaGetSymbolAddress((void**)&Qh,  g_Qh);  cudaGetSymbolAddress((void**)&Ql,  g_Ql);
    cudaGetSymbolAddress((void**)&Kh,  g_Kh);  cudaGetSymbolAddress((void**)&Kl,  g_Kl);
    cudaGetSymbolAddress((void**)&Vth, g_Vth); cudaGetSymbolAddress((void**)&Vtl, g_Vtl);
    cudaGetSymbolAddress((void**)&Oh,  g_Oh);  cudaGetSymbolAddress((void**)&Ol,  g_Ol);
    cudaGetSymbolAddress((void**)&WcTh, g_WcTh); cudaGetSymbolAddress((void**)&WcTl, g_WcTl);
    cudaGetSymbolAddress((void**)&WoTh, g_WoTh); cudaGetSymbolAddress((void**)&WoTl, g_WoTl);

    cudaFuncSetAttribute(bf16x3_gemm_kernel, cudaFuncAttributeMaxDynamicSharedMemorySize,
                         GM_SMEM_BYTES);
    cudaFuncSetAttribute(flash_kernel, cudaFuncAttributeMaxDynamicSharedMemorySize,
                         FLASH_SMEM_BYTES);

    // operand preparation (weights concatenated into one [3072][2048] operand)
    split_kernel<<<(TOKENS * HID) / 1024, 256>>>(X, Xh, Xl);
    transpose_split_kernel<<<dim3(2048 / 32, 2048 / 32), dim3(32, 8)>>>(
        Wq, WcTh, WcTl, 2048, 2048);
    transpose_split_kernel<<<dim3(512 / 32, 2048 / 32), dim3(32, 8)>>>(
        Wk, WcTh + (size_t)2048 * 2048, WcTl + (size_t)2048 * 2048, 2048, 512);
    transpose_split_kernel<<<dim3(512 / 32, 2048 / 32), dim3(32, 8)>>>(
        Wv, WcTh + (size_t)2560 * 2048, WcTl + (size_t)2560 * 2048, 2048, 512);
    transpose_split_kernel<<<dim3(2048 / 32, 2048 / 32), dim3(32, 8)>>>(
        Wo, WoTh, WoTl, 2048, 2048);

    // fused QKV projection: C[tok][0:2048]=Q, [2048:2560]=K, [2560:3072]=V
    bf16x3_gemm_kernel<<<dim3(NC / 128, TOKENS / 128), 256, GM_SMEM_BYTES>>>(
        Xh, Xl, WcTh, WcTl, C, TOKENS, NC, HID);

    // RMSNorm + RoPE -> planes; V transpose + split
    rmsnorm_rope_kernel<<<dim3(TOKENS, NH),  HD>>>(C, 0,    Qh, Ql, qw, cs, sn, NH);
    rmsnorm_rope_kernel<<<dim3(TOKENS, NKV), HD>>>(C, 2048, Kh, Kl, kw, cs, sn, NKV);
    vtrans_kernel<<<dim3(SEQ / 32, HD / 32, BATCH * NKV), dim3(32, 8)>>>(C, Vth, Vtl);

    // causal GQA flash attention (register-P, double-buffered)
    flash_kernel<<<dim3(SEQ / 128, NH, BATCH), 256, FLASH_SMEM_BYTES>>>(
        Qh, Ql, Kh, Kl, Vth, Vtl, Oh, Ol);

    // output projection
    bf16x3_gemm_kernel<<<dim3(2048 / 128, TOKENS / 128), 256, GM_SMEM_BYTES>>>(
        Oh, Ol, WoTh, WoTl, out, TOKENS, 2048, HID);
}

// round 17
// speedup vs baseline: 1.0012x; 1.0001x over previous
#include <cuda_runtime.h>
#include <cuda_bf16.h>
#include <math.h>
#include <stdint.h>

typedef __nv_bfloat16 bf16;

#define HID   2048
#define NH    16
#define NKV   4
#define HD    128
#define SEQ   2048
#define BATCH 2
#define TOKENS (BATCH*SEQ)
#define NC    3072   /* concatenated QKV output width */

// ---------------- scratch (no allocation allowed) ----------------
__device__ float g_C[(size_t)TOKENS * NC];                 // fused QKV GEMM out
__device__ bf16  g_Xh[(size_t)TOKENS * HID],      g_Xl[(size_t)TOKENS * HID];
__device__ bf16  g_Qh[(size_t)TOKENS * NH * HD],  g_Ql[(size_t)TOKENS * NH * HD];
__device__ bf16  g_Kh[(size_t)TOKENS * NKV * HD], g_Kl[(size_t)TOKENS * NKV * HD];
__device__ bf16  g_Vth[(size_t)BATCH * NKV * HD * SEQ], g_Vtl[(size_t)BATCH * NKV * HD * SEQ];
__device__ bf16  g_Oh[(size_t)TOKENS * NH * HD],  g_Ol[(size_t)TOKENS * NH * HD];
__device__ bf16  g_WcTh[(size_t)NC * 2048],  g_WcTl[(size_t)NC * 2048];   // Wq|Wk|Wv transposed
__device__ bf16  g_WoTh[(size_t)2048 * 2048], g_WoTl[(size_t)2048 * 2048];

// ---------------- helpers ----------------
__device__ __forceinline__ uint32_t smem_u32(const void* p) {
    uint32_t a;
    asm("{ .reg .u64 t; cvta.to.shared.u64 t, %1; cvt.u32.u64 %0, t; }" : "=r"(a) : "l"(p));
    return a;
}

#define CP_ASYNC16(dst, src) \
    asm volatile("cp.async.cg.shared.global [%0], [%1], 16;" :: "r"(dst), "l"(src))
#define CP_COMMIT() asm volatile("cp.async.commit_group;" ::: "memory")
#define CP_WAIT(n)  asm volatile("cp.async.wait_group %0;" :: "n"(n) : "memory")

__device__ __forceinline__ void ldsm_x4(uint32_t addr, uint32_t r[4]) {
    asm volatile("ldmatrix.sync.aligned.m8n8.x4.shared.b16 {%0,%1,%2,%3}, [%4];"
                 : "=r"(r[0]), "=r"(r[1]), "=r"(r[2]), "=r"(r[3]) : "r"(addr));
}
__device__ __forceinline__ void ldsm_x2(uint32_t addr, uint32_t r[2]) {
    asm volatile("ldmatrix.sync.aligned.m8n8.x2.shared.b16 {%0,%1}, [%2];"
                 : "=r"(r[0]), "=r"(r[1]) : "r"(addr));
}
__device__ __forceinline__ void mma_bf16(float c[4], const uint32_t a[4], const uint32_t b[2]) {
    asm volatile(
        "mma.sync.aligned.m16n8k16.row.col.f32.bf16.bf16.f32 "
        "{%0,%1,%2,%3}, {%4,%5,%6,%7}, {%8,%9}, {%0,%1,%2,%3};"
        : "+f"(c[0]), "+f"(c[1]), "+f"(c[2]), "+f"(c[3])
        : "r"(a[0]), "r"(a[1]), "r"(a[2]), "r"(a[3]), "r"(b[0]), "r"(b[1]));
}

__device__ __forceinline__ void fsplit2(float x, bf16& h, bf16& l) {
    h = __float2bfloat16(x);
    l = __float2bfloat16(x - __bfloat162float(h));
}
__device__ __forceinline__ uint32_t pack2(bf16 lo, bf16 hi) {
    __nv_bfloat162 t; t.x = lo; t.y = hi;
    return *reinterpret_cast<uint32_t*>(&t);
}

// ---------------- elementwise split: fp32 -> hi/lo planes ----------------
__global__ void split_kernel(const float* __restrict__ in,
                             bf16* __restrict__ hi, bf16* __restrict__ lo) {
    int i = (blockIdx.x * 256 + threadIdx.x) * 4;
    float4 v = *(const float4*)(in + i);
    bf16 h[4], l[4];
    fsplit2(v.x, h[0], l[0]); fsplit2(v.y, h[1], l[1]);
    fsplit2(v.z, h[2], l[2]); fsplit2(v.w, h[3], l[3]);
    *(uint2*)(hi + i) = *(uint2*)h;
    *(uint2*)(lo + i) = *(uint2*)l;
}

// ---------------- weight transpose + split: Wt[n][k] = W[k][n] ----------------
__global__ void transpose_split_kernel(const float* __restrict__ W,
                                       bf16* __restrict__ Wh, bf16* __restrict__ Wl,
                                       int K, int N) {
    __shared__ float t[32][33];
    int x = blockIdx.x * 32 + threadIdx.x;   // n
    int y0 = blockIdx.y * 32;                // k base
#pragma unroll
    for (int i = threadIdx.y; i < 32; i += 8)
        t[i][threadIdx.x] = W[(size_t)(y0 + i) * N + x];
    __syncthreads();
    int xo = y0 + threadIdx.x;               // k
    int yo0 = blockIdx.x * 32;               // n base
#pragma unroll
    for (int i = threadIdx.y; i < 32; i += 8) {
        bf16 h, l;
        fsplit2(t[threadIdx.x][i], h, l);
        Wh[(size_t)(yo0 + i) * K + xo] = h;
        Wl[(size_t)(yo0 + i) * K + xo] = l;
    }
}

// ---------------- V transpose + split from fused C: Vt[(b,kv,d)][s] ----------------
__global__ void vtrans_kernel(const float* __restrict__ C,
                              bf16* __restrict__ Vth, bf16* __restrict__ Vtl) {
    __shared__ float t[32][33];
    const int bkv = blockIdx.z;
    const int bb = bkv >> 2, kv = bkv & 3;
    const int s0 = blockIdx.x * 32, d0 = blockIdx.y * 32;
#pragma unroll
    for (int i = threadIdx.y; i < 32; i += 8)
        t[i][threadIdx.x] = C[(size_t)(bb * SEQ + s0 + i) * NC + 2560 + kv * HD + d0 + threadIdx.x];
    __syncthreads();
#pragma unroll
    for (int i = threadIdx.y; i < 32; i += 8) {
        bf16 h, l;
        fsplit2(t[threadIdx.x][i], h, l);
        size_t idx = (size_t)(bkv * HD + d0 + i) * SEQ + s0 + threadIdx.x;
        Vth[idx] = h; Vtl[idx] = l;
    }
}

// ---------------- bf16x3 GEMM: C[M,N] = A[M,K] @ Bt[N,K]^T ----------------
#define GROWB 80
#define GPLANE (128 * GROWB)
#define GSTAGE_BYTES (4 * GPLANE)
#define GM_SMEM_BYTES (2 * GSTAGE_BYTES)

__global__ __launch_bounds__(256, 2)
void bf16x3_gemm_kernel(const bf16* __restrict__ Ah, const bf16* __restrict__ Al,
                        const bf16* __restrict__ Bh, const bf16* __restrict__ Bl,
                        float* __restrict__ C, int M, int N, int K) {
    extern __shared__ char gsm[];
    const uint32_t sbase = smem_u32(gsm);

    const int tid = threadIdx.x;
    const int wid = tid >> 5, l = tid & 31;
    const int wm = wid >> 2, wn = wid & 3;
    const int bn = blockIdx.x, bm = blockIdx.y;

    const bf16* src[4] = { Ah + (size_t)bm * 128 * K, Al + (size_t)bm * 128 * K,
                           Bh + (size_t)bn * 128 * K, Bl + (size_t)bn * 128 * K };
    const int KT = K >> 5;

    const int a_sel = l & 15;
    const uint32_t a_kB = (uint32_t)(l >> 4) * 16;
    const int b_sel = l & 7;
    const uint32_t b_kB = (uint32_t)((l >> 3) & 1) * 16;

    float acc[4][4][4];
#pragma unroll
    for (int mt = 0; mt < 4; mt++)
#pragma unroll
        for (int nt = 0; nt < 4; nt++)
#pragma unroll
            for (int r = 0; r < 4; r++) acc[mt][nt][r] = 0.f;

    auto load_stage = [&](int s, int kt) {
        uint32_t base = sbase + s * GSTAGE_BYTES;
        int k0 = kt << 5;
#pragma unroll
        for (int pl = 0; pl < 4; pl++)
#pragma unroll
            for (int half = 0; half < 2; half++) {
                int cid = half * 256 + tid;
                int row = cid >> 2, ch = cid & 3;
                CP_ASYNC16(base + pl * GPLANE + row * GROWB + ch * 16,
                           src[pl] + (size_t)row * K + k0 + ch * 8);
            }
    };

    load_stage(0, 0);
    CP_COMMIT();

    for (int kt = 0; kt < KT; kt++) {
        const int s = kt & 1;
        CP_WAIT(0);
        __syncthreads();
        if (kt + 1 < KT) { load_stage(s ^ 1, kt + 1); CP_COMMIT(); }

        const uint32_t base = sbase + s * GSTAGE_BYTES;

#pragma unroll
        for (int ks = 0; ks < 2; ks++) {
            const uint32_t kB = ks * 32;
            uint32_t bh[4][2], bl[4][2];
#pragma unroll
            for (int nt = 0; nt < 4; nt++) {
                uint32_t boff = (wn * 32 + nt * 8 + b_sel) * GROWB + kB + b_kB;
                ldsm_x2(base + 2 * GPLANE + boff, bh[nt]);
                ldsm_x2(base + 3 * GPLANE + boff, bl[nt]);
            }
#pragma unroll
            for (int mt = 0; mt < 4; mt++) {
                uint32_t ah[4], al[4];
                uint32_t aoff = (wm * 64 + mt * 16 + a_sel) * GROWB + kB + a_kB;
                ldsm_x4(base + aoff, ah);
                ldsm_x4(base + GPLANE + aoff, al);
#pragma unroll
                for (int nt = 0; nt < 4; nt++) {
                    mma_bf16(acc[mt][nt], al, bh[nt]);
                    mma_bf16(acc[mt][nt], ah, bl[nt]);
                    mma_bf16(acc[mt][nt], ah, bh[nt]);
                }
            }
        }
        __syncthreads();
    }

    const int er = l >> 2, ec = (l & 3) * 2;
#pragma unroll
    for (int mt = 0; mt < 4; mt++) {
        int row = bm * 128 + wm * 64 + mt * 16 + er;
#pragma unroll
        for (int nt = 0; nt < 4; nt++) {
            int col = bn * 128 + wn * 32 + nt * 8 + ec;
            *(float2*)(C + (size_t)row * N + col) =
                make_float2(acc[mt][nt][0], acc[mt][nt][1]);
            *(float2*)(C + (size_t)(row + 8) * N + col) =
                make_float2(acc[mt][nt][2], acc[mt][nt][3]);
        }
    }
}

// ---------------- fused RMSNorm + RoPE (reads fused C) -> bf16 hi/lo planes ----------------
__global__ void rmsnorm_rope_kernel(const float* __restrict__ C, int in_off,
                                    bf16* __restrict__ Xh, bf16* __restrict__ Xl,
                                    const float* __restrict__ w,
                                    const float* __restrict__ cs, const float* __restrict__ sn,
                                    int nheads) {
    const int tok = blockIdx.x;
    const int h   = blockIdx.y;
    const int d   = threadIdx.x;
    const int s   = tok & (SEQ - 1);

    const float* row = C + (size_t)tok * NC + in_off + h * HD;
    float x = row[d];

    float ss = x * x;
#pragma unroll
    for (int o = 16; o > 0; o >>= 1) ss += __shfl_xor_sync(0xffffffffu, ss, o);

    __shared__ float wsum[4];
    __shared__ float sv[HD];
    if ((d & 31) == 0) wsum[d >> 5] = ss;
    __syncthreads();
    float tot = wsum[0] + wsum[1] + wsum[2] + wsum[3];
    float r = rsqrtf(tot * (1.0f / HD) + 1e-6f);
    float v = x * r * w[d];
    sv[d] = v;
    __syncthreads();
    float rot = (d < 64) ? -sv[d + 64] : sv[d - 64];
    float y = v * cs[(size_t)s * HD + d] + rot * sn[(size_t)s * HD + d];
    bf16 hh, ll;
    fsplit2(y, hh, ll);
    size_t idx = (size_t)tok * nheads * HD + h * HD + d;
    Xh[idx] = hh; Xl[idx] = ll;
}

// ---------------- tensor-core causal flash attention (bf16x3), warp-owned rows ----------------
// CTA: 128 q rows, 8 warps x 16 rows. Per iter: 64 kv, double-buffered cp.async.
// P kept in registers (C-fragment -> A-fragment reuse). All softmax warp-local.
#define FQ_S 272                              /* Q/K row stride bytes */
#define FV_S 144                              /* V row stride bytes */
#define QPL (128 * FQ_S)                      /* 34816 per Q plane */
#define KPL (64 * FQ_S)                       /* 17408 per K plane */
#define VPL (128 * FV_S)                      /* 18432 per V plane */
#define OFF_K0 (2 * QPL)
#define KV_STAGE (2 * KPL + 2 * VPL)          /* 71680 */
#define FLASH_SMEM_BYTES (2 * QPL + 2 * KV_STAGE)   /* 212992 */

__global__ __launch_bounds__(256, 1)
void flash_kernel(const bf16* __restrict__ Qh, const bf16* __restrict__ Ql,
                  const bf16* __restrict__ Kh, const bf16* __restrict__ Kl,
                  const bf16* __restrict__ Vth, const bf16* __restrict__ Vtl,
                  bf16* __restrict__ Oh, bf16* __restrict__ Ol) {
    extern __shared__ char fsmc[];
    const uint32_t sb = smem_u32(fsmc);

    const int qt = blockIdx.x, h = blockIdx.y, b = blockIdx.z;
    const int kvh = h >> 2;
    const int tid = threadIdx.x, wid = tid >> 5, l = tid & 31;
    const float scale = 0.08838834764831845f;

    const int a_sel = l & 15;
    const uint32_t a_kB = (uint32_t)(l >> 4) * 16;
    const int b4 = ((l >> 4) & 1) * 8 + (l & 7);       // x4 B: two n8 tiles per load
    const uint32_t b_kB = (uint32_t)((l >> 3) & 1) * 16;
    const int qrow = l >> 2, qcol = (l & 3) * 2;

    // Q tiles (both planes), once
    {
        const bf16* qsrc[2] = { Qh + (size_t)(b * SEQ + qt * 128) * (NH * HD) + h * HD,
                                Ql + (size_t)(b * SEQ + qt * 128) * (NH * HD) + h * HD };
#pragma unroll
        for (int t = 0; t < 16; t++) {
            int c = tid + t * 256;
            int pl = c >> 11, cid = c & 2047;
            int r = cid >> 4, ch = cid & 15;
            CP_ASYNC16(sb + pl * QPL + r * FQ_S + ch * 16,
                       qsrc[pl] + (size_t)r * (NH * HD) + ch * 8);
        }
    }
    CP_COMMIT();

    const bf16* ksrc[2] = { Kh + (size_t)(b * SEQ) * (NKV * HD) + kvh * HD,
                            Kl + (size_t)(b * SEQ) * (NKV * HD) + kvh * HD };
    const bf16* vsrc[2] = { Vth + (size_t)(b * NKV + kvh) * HD * SEQ,
                            Vtl + (size_t)(b * NKV + kvh) * HD * SEQ };

    auto load_kv = [&](int jt, int st) {
        uint32_t kb = sb + OFF_K0 + st * KV_STAGE;
        uint32_t vb = kb + 2 * KPL;
#pragma unroll
        for (int t = 0; t < 8; t++) {
            int c = tid + t * 256;
            int pl = c >> 10, cid = c & 1023;
            int r = cid >> 4, ch = cid & 15;
            CP_ASYNC16(kb + pl * KPL + r * FQ_S + ch * 16,
                       ksrc[pl] + (size_t)(jt * 64 + r) * (NKV * HD) + ch * 8);
        }
#pragma unroll
        for (int t = 0; t < 8; t++) {
            int c = tid + t * 256;
            int pl = c >> 10, cid = c & 1023;
            int r = cid >> 3, ch = cid & 7;
            CP_ASYNC16(vb + pl * VPL + r * FV_S + ch * 16,
                       vsrc[pl] + (size_t)r * SEQ + jt * 64 + ch * 8);
        }
    };
    load_kv(0, 0);
    CP_COMMIT();

    float m[2] = { -1e30f, -1e30f }, lsum[2] = { 0.f, 0.f };
    float oacc[16][4];
#pragma unroll
    for (int nto = 0; nto < 16; nto++)
#pragma unroll
        for (int e = 0; e < 4; e++) oacc[nto][e] = 0.f;

    const int jt_end = 2 * qt + 2;
    for (int jt = 0; jt < jt_end; jt++) {
        const int st = jt & 1;
        CP_WAIT(0);
        __syncthreads();
        if (jt + 1 < jt_end) { load_kv(jt + 1, st ^ 1); CP_COMMIT(); }
        const uint32_t kb = sb + OFF_K0 + st * KV_STAGE;
        const uint32_t vb = kb + 2 * KPL;

        // S = Q @ K^T : warp stripe 16x64, 8 k16 steps, 3-term
        float sacc[8][4];
#pragma unroll
        for (int nt = 0; nt < 8; nt++)
#pragma unroll
            for (int e = 0; e < 4; e++) sacc[nt][e] = 0.f;

#pragma unroll
        for (int ks = 0; ks < 8; ks++) {
            const uint32_t kB = ks * 32;
            uint32_t ah[4], al[4];
            uint32_t aoff = (uint32_t)(wid * 16 + a_sel) * FQ_S + kB + a_kB;
            ldsm_x4(sb + aoff, ah);
            ldsm_x4(sb + QPL + aoff, al);
#pragma unroll
            for (int ntp = 0; ntp < 4; ntp++) {
                uint32_t bh4[4], bl4[4];
                uint32_t boff = (uint32_t)(ntp * 16 + b4) * FQ_S + kB + b_kB;
                ldsm_x4(kb + boff, bh4);
                ldsm_x4(kb + KPL + boff, bl4);
                mma_bf16(sacc[2 * ntp],     al, bh4);
                mma_bf16(sacc[2 * ntp],     ah, bl4);
                mma_bf16(sacc[2 * ntp],     ah, bh4);
                mma_bf16(sacc[2 * ntp + 1], al, bh4 + 2);
                mma_bf16(sacc[2 * ntp + 1], ah, bl4 + 2);
                mma_bf16(sacc[2 * ntp + 1], ah, bh4 + 2);
            }
        }

        // scale + causal mask + warp-local row max
        const bool need_mask = (jt >= 2 * qt);
        float lmax[2] = { -1e30f, -1e30f };
#pragma unroll
        for (int nt = 0; nt < 8; nt++)
#pragma unroll
            for (int e = 0; e < 4; e++) {
                int h2 = e >> 1;
                float val = sacc[nt][e] * scale;
                if (need_mask) {
                    int gr = qt * 128 + wid * 16 + qrow + 8 * h2;
                    int gc = jt * 64 + nt * 8 + qcol + (e & 1);
                    if (gc > gr) val = -1e30f;
                }
                sacc[nt][e] = val;
                lmax[h2] = fmaxf(lmax[h2], val);
            }

        float alpha[2];
#pragma unroll
        for (int h2 = 0; h2 < 2; h2++) {
            float v = lmax[h2];
            v = fmaxf(v, __shfl_xor_sync(0xffffffffu, v, 1));
            v = fmaxf(v, __shfl_xor_sync(0xffffffffu, v, 2));
            float mn = fmaxf(m[h2], v);
            alpha[h2] = __expf(m[h2] - mn);
            m[h2] = mn;
        }

        // p = exp(s-m): pack A-fragments (hi/lo) in registers
        float ls[2] = { 0.f, 0.f };
        uint32_t pfh[4][4], pfl[4][4];
#pragma unroll
        for (int ks2 = 0; ks2 < 4; ks2++)
#pragma unroll
            for (int half = 0; half < 2; half++) {
                int nt = 2 * ks2 + half;
                float p0 = __expf(sacc[nt][0] - m[0]);
                float p1 = __expf(sacc[nt][1] - m[0]);
                float p2 = __expf(sacc[nt][2] - m[1]);
                float p3 = __expf(sacc[nt][3] - m[1]);
                ls[0] += p0 + p1;
                ls[1] += p2 + p3;
                bf16 a0 = __float2bfloat16(p0), a1 = __float2bfloat16(p1);
                bf16 a2 = __float2bfloat16(p2), a3 = __float2bfloat16(p3);
                pfh[ks2][half * 2 + 0] = pack2(a0, a1);
                pfh[ks2][half * 2 + 1] = pack2(a2, a3);
                pfl[ks2][half * 2 + 0] =
                    pack2(__float2bfloat16(p0 - __bfloat162float(a0)),
                          __float2bfloat16(p1 - __bfloat162float(a1)));
                pfl[ks2][half * 2 + 1] =
                    pack2(__float2bfloat16(p2 - __bfloat162float(a2)),
                          __float2bfloat16(p3 - __bfloat162float(a3)));
            }
#pragma unroll
        for (int h2 = 0; h2 < 2; h2++) {
            float v = ls[h2];
            v += __shfl_xor_sync(0xffffffffu, v, 1);
            v += __shfl_xor_sync(0xffffffffu, v, 2);
            lsum[h2] = lsum[h2] * alpha[h2] + v;
        }
#pragma unroll
        for (int nto = 0; nto < 16; nto++)
#pragma unroll
            for (int e = 0; e < 4; e++) oacc[nto][e] *= alpha[e >> 1];

        // O += P @ V : 4 k16 steps over s, 16 n8 tiles over d, 3-term
#pragma unroll
        for (int ks2 = 0; ks2 < 4; ks2++) {
            const uint32_t kB = ks2 * 32;
#pragma unroll
            for (int ntp = 0; ntp < 8; ntp++) {
                uint32_t vh4[4], vl4[4];
                uint32_t boff = (uint32_t)(ntp * 16 + b4) * FV_S + kB + b_kB;
                ldsm_x4(vb + boff, vh4);
                ldsm_x4(vb + VPL + boff, vl4);
                mma_bf16(oacc[2 * ntp],     pfl[ks2], vh4);
                mma_bf16(oacc[2 * ntp],     pfh[ks2], vl4);
                mma_bf16(oacc[2 * ntp],     pfh[ks2], vh4);
                mma_bf16(oacc[2 * ntp + 1], pfl[ks2], vh4 + 2);
                mma_bf16(oacc[2 * ntp + 1], pfh[ks2], vl4 + 2);
                mma_bf16(oacc[2 * ntp + 1], pfh[ks2], vh4 + 2);
            }
        }
    }

    // epilogue: normalize, split, store hi/lo planes
    bf16* Ogh = Oh + (size_t)(b * SEQ + qt * 128) * (NH * HD) + h * HD;
    bf16* Ogl = Ol + (size_t)(b * SEQ + qt * 128) * (NH * HD) + h * HD;
#pragma unroll
    for (int h2 = 0; h2 < 2; h2++) {
        int r = wid * 16 + qrow + 8 * h2;
        float inv = 1.0f / lsum[h2];
#pragma unroll
        for (int nto = 0; nto < 16; nto++) {
            int c = nto * 8 + qcol;
            float v0 = oacc[nto][h2 * 2 + 0] * inv;
            float v1 = oacc[nto][h2 * 2 + 1] * inv;
            bf16 h0 = __float2bfloat16(v0), h1b = __float2bfloat16(v1);
            *(uint32_t*)(Ogh + (size_t)r * (NH * HD) + c) = pack2(h0, h1b);
            *(uint32_t*)(Ogl + (size_t)r * (NH * HD) + c) =
                pack2(__float2bfloat16(v0 - __bfloat162float(h0)),
                      __float2bfloat16(v1 - __bfloat162float(h1b)));
        }
    }
}

// ---------------- launch ----------------
extern "C" void kernel_launch(void* const* d_in, const int* in_sizes, int n_in,
                              void* d_out, int out_size) {
    const float* X  = (const float*)d_in[0];
    const float* cs = (const float*)d_in[1];
    const float* sn = (const float*)d_in[2];
    const float* Wq = (const float*)d_in[3];
    const float* Wk = (const float*)d_in[4];
    const float* Wv = (const float*)d_in[5];
    const float* Wo = (const float*)d_in[6];
    const float* qw = (const float*)d_in[7];
    const float* kw = (const float*)d_in[8];
    float* out = (float*)d_out;

    float* C;
    bf16 *Xh, *Xl, *Qh, *Ql, *Kh, *Kl, *Vth, *Vtl, *Oh, *Ol;
    bf16 *WcTh, *WcTl, *WoTh, *WoTl;
    cudaGetSymbolAddress((void**)&C,   g_C);
    cudaGetSymbolAddress((void**)&Xh,  g_Xh);  cudaGetSymbolAddress((void**)&Xl,  g_Xl);
    cudaGetSymbolAddress((void**)&Qh,  g_Qh);  cudaGetSymbolAddress((void**)&Ql,  g_Ql);
    cudaGetSymbolAddress((void**)&Kh,  g_Kh);  cudaGetSymbolAddress((void**)&Kl,  g_Kl);
    cudaGetSymbolAddress((void**)&Vth, g_Vth); cudaGetSymbolAddress((void**)&Vtl, g_Vtl);
    cudaGetSymbolAddress((void**)&Oh,  g_Oh);  cudaGetSymbolAddress((void**)&Ol,  g_Ol);
    cudaGetSymbolAddress((void**)&WcTh, g_WcTh); cudaGetSymbolAddress((void**)&WcTl, g_WcTl);
    cudaGetSymbolAddress((void**)&WoTh, g_WoTh); cudaGetSymbolAddress((void**)&WoTl, g_WoTl);

    cudaFuncSetAttribute(bf16x3_gemm_kernel, cudaFuncAttributeMaxDynamicSharedMemorySize,
                         GM_SMEM_BYTES);
    cudaFuncSetAttribute(flash_kernel, cudaFuncAttributeMaxDynamicSharedMemorySize,
                         FLASH_SMEM_BYTES);

    // operand preparation (weights concatenated into one [3072][2048] operand)
    split_kernel<<<(TOKENS * HID) / 1024, 256>>>(X, Xh, Xl);
    transpose_split_kernel<<<dim3(2048 / 32, 2048 / 32), dim3(32, 8)>>>(
        Wq, WcTh, WcTl, 2048, 2048);
    transpose_split_kernel<<<dim3(512 / 32, 2048 / 32), dim3(32, 8)>>>(
        Wk, WcTh + (size_t)2048 * 2048, WcTl + (size_t)2048 * 2048, 2048, 512);
    transpose_split_kernel<<<dim3(512 / 32, 2048 / 32), dim3(32, 8)>>>(
        Wv, WcTh + (size_t)2560 * 2048, WcTl + (size_t)2560 * 2048, 2048, 512);
    transpose_split_kernel<<<dim3(2048 / 32, 2048 / 32), dim3(32, 8)>>>(
        Wo, WoTh, WoTl, 2048, 2048);

    // fused QKV projection: C[tok][0:2048]=Q, [2048:2560]=K, [2560:3072]=V
    bf16x3_gemm_kernel<<<dim3(NC / 128, TOKENS / 128), 256, GM_SMEM_BYTES>>>(
        Xh, Xl, WcTh, WcTl, C, TOKENS, NC, HID);

    // RMSNorm + RoPE -> planes; V transpose + split
    rmsnorm_rope_kernel<<<dim3(TOKENS, NH),  HD>>>(C, 0,    Qh, Ql, qw, cs, sn, NH);
    rmsnorm_rope_kernel<<<dim3(TOKENS, NKV), HD>>>(C, 2048, Kh, Kl, kw, cs, sn, NKV);
    vtrans_kernel<<<dim3(SEQ / 32, HD / 32, BATCH * NKV), dim3(32, 8)>>>(C, Vth, Vtl);

    // causal GQA flash attention (register-P, double-buffered)
    flash_kernel<<<dim3(SEQ / 128, NH, BATCH), 256, FLASH_SMEM_BYTES>>>(
        Qh, Ql, Kh, Kl, Vth, Vtl, Oh, Ol);

    // output projection
    bf16x3_gemm_kernel<<<dim3(2048 / 128, TOKENS / 128), 256, GM_SMEM_BYTES>>>(
        Oh, Ol, WoTh, WoTl, out, TOKENS, 2048, HID);
}